// round 1
// baseline (speedup 1.0000x reference)
#include <cuda_runtime.h>
#include <math.h>

// Problem constants (fixed shapes per reference)
#define N_ROWS 32768     // 32*32*32
#define DIM    256
#define KCODES 8192
#define NZ     (N_ROWS * DIM)   // 8388608

// GEMM-argmin tiling
#define BM 128
#define BN 128
#define BK 64
#define ZS_STRIDE 132    // padded row stride (floats) to avoid bank conflicts
#define SMEM_BYTES ((DIM * ZS_STRIDE + BK * ZS_STRIDE) * 4)  // 168960

__device__ float  g_esq[KCODES];
__device__ int    g_idx[N_ROWS];
__device__ int    g_cnt[KCODES];
__device__ double g_sse;

// ---------------------------------------------------------------------------
// Kernel 1: per-code squared norms
// ---------------------------------------------------------------------------
__global__ void k_esq(const float* __restrict__ cb) {
    int c = blockIdx.x * blockDim.x + threadIdx.x;
    if (c < KCODES) {
        const float4* p = (const float4*)(cb + (size_t)c * DIM);
        float s = 0.f;
#pragma unroll 8
        for (int i = 0; i < DIM / 4; ++i) {
            float4 v = p[i];
            s += v.x * v.x + v.y * v.y + v.z * v.z + v.w * v.w;
        }
        g_esq[c] = s;
    }
}

// ---------------------------------------------------------------------------
// Kernel 2: fused GEMM + argmin.
// dist(row, code) = ||e||^2 - 2 * <z_row, e_code>   (||z||^2 constant per row)
// Block: 256 threads (16x16), each thread owns an 8x8 microtile.
// Block tile: 128 rows x 128 codes, K streamed in chunks of 64.
// z tile (128 x 256) kept resident in smem (k-major, padded).
// ---------------------------------------------------------------------------
__global__ void __launch_bounds__(256, 1)
k_argmin(const float* __restrict__ z, const float* __restrict__ cb) {
    extern __shared__ float sm[];
    float* zs = sm;                         // [DIM][ZS_STRIDE] k-major
    float* es = sm + DIM * ZS_STRIDE;       // [BK][ZS_STRIDE]  k-major

    const int tid  = threadIdx.x;
    const int tx   = tid & 15;              // code group (8 codes)
    const int ty   = tid >> 4;              // row group (8 rows)
    const int row0 = blockIdx.x * BM;

    // Load + transpose the z tile: zs[k][row] = z[row0+row][k]
    // thread walks a fixed row with stride 32B (L1-line friendly)
    for (int t = tid; t < BM * (DIM / 4); t += 256) {
        int k4  = t >> 7;                   // 0..63
        int row = t & 127;
        float4 v = *(const float4*)(z + (size_t)(row0 + row) * DIM + k4 * 4);
        zs[(4 * k4 + 0) * ZS_STRIDE + row] = v.x;
        zs[(4 * k4 + 1) * ZS_STRIDE + row] = v.y;
        zs[(4 * k4 + 2) * ZS_STRIDE + row] = v.z;
        zs[(4 * k4 + 3) * ZS_STRIDE + row] = v.w;
    }

    float bestD[8];
    int   bestI[8];
#pragma unroll
    for (int i = 0; i < 8; ++i) { bestD[i] = INFINITY; bestI[i] = 0; }

    for (int c0 = 0; c0 < KCODES; c0 += BN) {
        float acc[8][8];
#pragma unroll
        for (int i = 0; i < 8; ++i)
#pragma unroll
            for (int j = 0; j < 8; ++j) acc[i][j] = 0.f;

        for (int kb = 0; kb < DIM; kb += BK) {
            __syncthreads();   // protect previous es contents
            // Load es tile: es[k][code] = cb[c0+code][kb+k], 128 codes x 64 k
            for (int t = tid; t < BN * (BK / 4); t += 256) {
                int k4   = t >> 7;          // 0..15
                int code = t & 127;
                float4 v = *(const float4*)(cb + (size_t)(c0 + code) * DIM + kb + k4 * 4);
                es[(4 * k4 + 0) * ZS_STRIDE + code] = v.x;
                es[(4 * k4 + 1) * ZS_STRIDE + code] = v.y;
                es[(4 * k4 + 2) * ZS_STRIDE + code] = v.z;
                es[(4 * k4 + 3) * ZS_STRIDE + code] = v.w;
            }
            __syncthreads();

#pragma unroll 8
            for (int k = 0; k < BK; ++k) {
                const float* zp = &zs[(size_t)(kb + k) * ZS_STRIDE + ty * 8];
                const float* ep = &es[(size_t)k * ZS_STRIDE + tx * 8];
                float zf[8], ef[8];
                *(float4*)&zf[0] = *(const float4*)(zp);
                *(float4*)&zf[4] = *(const float4*)(zp + 4);
                *(float4*)&ef[0] = *(const float4*)(ep);
                *(float4*)&ef[4] = *(const float4*)(ep + 4);
#pragma unroll
                for (int i = 0; i < 8; ++i)
#pragma unroll
                    for (int j = 0; j < 8; ++j)
                        acc[i][j] = fmaf(zf[i], ef[j], acc[i][j]);
            }
        }

        // Chunk epilogue: fold into running argmin (codes ascending -> strict <
        // keeps the lowest index on exact ties, matching jnp.argmin)
#pragma unroll
        for (int j = 0; j < 8; ++j) {
            int code = c0 + tx * 8 + j;
            float eq = g_esq[code];
#pragma unroll
            for (int i = 0; i < 8; ++i) {
                float d = eq - 2.0f * acc[i][j];
                if (d < bestD[i]) { bestD[i] = d; bestI[i] = code; }
            }
        }
    }

    // Cross-lane reduce over the 16 code-groups (width=16 keeps row groups apart)
#pragma unroll
    for (int off = 8; off > 0; off >>= 1) {
#pragma unroll
        for (int i = 0; i < 8; ++i) {
            float od = __shfl_down_sync(0xffffffffu, bestD[i], off, 16);
            int   oi = __shfl_down_sync(0xffffffffu, bestI[i], off, 16);
            if (od < bestD[i] || (od == bestD[i] && oi < bestI[i])) {
                bestD[i] = od; bestI[i] = oi;
            }
        }
    }
    if (tx == 0) {
#pragma unroll
        for (int i = 0; i < 8; ++i)
            g_idx[row0 + ty * 8 + i] = bestI[i];
    }
}

// ---------------------------------------------------------------------------
// Kernel 3: zero accumulators (graph replays must be deterministic)
// ---------------------------------------------------------------------------
__global__ void k_zero() {
    int t = blockIdx.x * blockDim.x + threadIdx.x;
    if (t < KCODES) g_cnt[t] = 0;
    if (t == 0) g_sse = 0.0;
}

// ---------------------------------------------------------------------------
// Kernel 4: gather z_q, write z_q_st = z_e + (z_q - z_e), indices (as float),
// accumulate SSE and histogram counts. One warp per row.
// ---------------------------------------------------------------------------
__global__ void k_gather(const float* __restrict__ z, const float* __restrict__ cb,
                         float* __restrict__ out) {
    int gwarp = (blockIdx.x * blockDim.x + threadIdx.x) >> 5;
    int lane  = threadIdx.x & 31;
    if (gwarp >= N_ROWS) return;
    int row = gwarp;
    int idx = g_idx[row];

    const float4* q  = (const float4*)(cb + (size_t)idx * DIM);
    const float4* ze = (const float4*)(z + (size_t)row * DIM);
    float4*       o  = (float4*)(out + (size_t)row * DIM);

    float s = 0.f;
#pragma unroll
    for (int i = 0; i < 2; ++i) {
        int c = lane + i * 32;
        float4 a = ze[c];
        float4 b = q[c];
        float4 r;
        r.x = a.x + (b.x - a.x);
        r.y = a.y + (b.y - a.y);
        r.z = a.z + (b.z - a.z);
        r.w = a.w + (b.w - a.w);
        float dx = a.x - b.x, dy = a.y - b.y, dz = a.z - b.z, dw = a.w - b.w;
        s += dx * dx + dy * dy + dz * dz + dw * dw;
        o[c] = r;
    }
#pragma unroll
    for (int off = 16; off > 0; off >>= 1)
        s += __shfl_down_sync(0xffffffffu, s, off);

    if (lane == 0) {
        atomicAdd(&g_sse, (double)s);
        atomicAdd(&g_cnt[idx], 1);
        out[NZ + row] = (float)idx;       // indices output (cast to float)
    }
}

// ---------------------------------------------------------------------------
// Kernel 5: loss + perplexity scalars
// ---------------------------------------------------------------------------
__global__ void k_final(float* __restrict__ out) {
    __shared__ float red[256];
    int t = threadIdx.x;
    float h = 0.f;
    for (int c = t; c < KCODES; c += 256) {
        float avg = (float)g_cnt[c] / (float)N_ROWS;
        h += avg * logf(avg + 1e-12f);
    }
    red[t] = h;
    __syncthreads();
    for (int s = 128; s > 0; s >>= 1) {
        if (t < s) red[t] += red[t + s];
        __syncthreads();
    }
    if (t == 0) {
        double mse = g_sse / (double)((size_t)N_ROWS * DIM);
        out[NZ + N_ROWS]     = (float)(1.25 * mse);   // codebook_loss + 0.25*commitment
        out[NZ + N_ROWS + 1] = expf(-red[0]);         // perplexity
    }
}

// ---------------------------------------------------------------------------
extern "C" void kernel_launch(void* const* d_in, const int* in_sizes, int n_in,
                              void* d_out, int out_size) {
    const float* z  = (const float*)d_in[0];   // z_e   [32,32,32,256]
    const float* cb = (const float*)d_in[1];   // codebook [8192,256]
    float* out = (float*)d_out;

    cudaFuncSetAttribute(k_argmin, cudaFuncAttributeMaxDynamicSharedMemorySize,
                         SMEM_BYTES);

    k_esq<<<KCODES / 256, 256>>>(cb);
    k_argmin<<<N_ROWS / BM, 256, SMEM_BYTES>>>(z, cb);
    k_zero<<<KCODES / 256, 256>>>();
    k_gather<<<(N_ROWS * 32) / 256, 256>>>(z, cb, out);
    k_final<<<1, 256>>>(out);
}

// round 2
// speedup vs baseline: 1.0005x; 1.0005x over previous
#include <cuda_runtime.h>
#include <math.h>

// Problem constants (fixed shapes per reference)
#define N_ROWS 32768     // 32*32*32
#define DIM    256
#define KCODES 8192
#define NZ     (N_ROWS * DIM)   // 8388608

// GEMM-argmin tiling
#define BM 128
#define BN 128
#define BK 64
#define ZS_STRIDE 132    // padded row stride (floats) to avoid bank conflicts
#define SMEM_BYTES ((DIM * ZS_STRIDE + BK * ZS_STRIDE) * 4)  // 168960

__device__ float  g_esq[KCODES];
__device__ int    g_idx[N_ROWS];
__device__ int    g_cnt[KCODES];
__device__ double g_sse;

// ---------------------------------------------------------------------------
// Kernel 1: per-code squared norms
// ---------------------------------------------------------------------------
__global__ void k_esq(const float* __restrict__ cb) {
    int c = blockIdx.x * blockDim.x + threadIdx.x;
    if (c < KCODES) {
        const float4* p = (const float4*)(cb + (size_t)c * DIM);
        float s = 0.f;
#pragma unroll 8
        for (int i = 0; i < DIM / 4; ++i) {
            float4 v = p[i];
            s += v.x * v.x + v.y * v.y + v.z * v.z + v.w * v.w;
        }
        g_esq[c] = s;
    }
}

// ---------------------------------------------------------------------------
// Kernel 2: fused GEMM + argmin.
// dist(row, code) = ||e||^2 - 2 * <z_row, e_code>   (||z||^2 constant per row)
// Block: 256 threads (16x16), each thread owns an 8x8 microtile.
// Block tile: 128 rows x 128 codes, K streamed in chunks of 64.
// z tile (128 x 256) kept resident in smem (k-major, padded).
// ---------------------------------------------------------------------------
__global__ void __launch_bounds__(256, 1)
k_argmin(const float* __restrict__ z, const float* __restrict__ cb) {
    extern __shared__ float sm[];
    float* zs = sm;                         // [DIM][ZS_STRIDE] k-major
    float* es = sm + DIM * ZS_STRIDE;       // [BK][ZS_STRIDE]  k-major

    const int tid  = threadIdx.x;
    const int tx   = tid & 15;              // code group (8 codes)
    const int ty   = tid >> 4;              // row group (8 rows)
    const int row0 = blockIdx.x * BM;

    // Load + transpose the z tile: zs[k][row] = z[row0+row][k]
    // thread walks a fixed row with stride 32B (L1-line friendly)
    for (int t = tid; t < BM * (DIM / 4); t += 256) {
        int k4  = t >> 7;                   // 0..63
        int row = t & 127;
        float4 v = *(const float4*)(z + (size_t)(row0 + row) * DIM + k4 * 4);
        zs[(4 * k4 + 0) * ZS_STRIDE + row] = v.x;
        zs[(4 * k4 + 1) * ZS_STRIDE + row] = v.y;
        zs[(4 * k4 + 2) * ZS_STRIDE + row] = v.z;
        zs[(4 * k4 + 3) * ZS_STRIDE + row] = v.w;
    }

    float bestD[8];
    int   bestI[8];
#pragma unroll
    for (int i = 0; i < 8; ++i) { bestD[i] = INFINITY; bestI[i] = 0; }

    for (int c0 = 0; c0 < KCODES; c0 += BN) {
        float acc[8][8];
#pragma unroll
        for (int i = 0; i < 8; ++i)
#pragma unroll
            for (int j = 0; j < 8; ++j) acc[i][j] = 0.f;

        for (int kb = 0; kb < DIM; kb += BK) {
            __syncthreads();   // protect previous es contents
            // Load es tile: es[k][code] = cb[c0+code][kb+k], 128 codes x 64 k
            for (int t = tid; t < BN * (BK / 4); t += 256) {
                int k4   = t >> 7;          // 0..15
                int code = t & 127;
                float4 v = *(const float4*)(cb + (size_t)(c0 + code) * DIM + kb + k4 * 4);
                es[(4 * k4 + 0) * ZS_STRIDE + code] = v.x;
                es[(4 * k4 + 1) * ZS_STRIDE + code] = v.y;
                es[(4 * k4 + 2) * ZS_STRIDE + code] = v.z;
                es[(4 * k4 + 3) * ZS_STRIDE + code] = v.w;
            }
            __syncthreads();

#pragma unroll 8
            for (int k = 0; k < BK; ++k) {
                const float* zp = &zs[(size_t)(kb + k) * ZS_STRIDE + ty * 8];
                const float* ep = &es[(size_t)k * ZS_STRIDE + tx * 8];
                float zf[8], ef[8];
                *(float4*)&zf[0] = *(const float4*)(zp);
                *(float4*)&zf[4] = *(const float4*)(zp + 4);
                *(float4*)&ef[0] = *(const float4*)(ep);
                *(float4*)&ef[4] = *(const float4*)(ep + 4);
#pragma unroll
                for (int i = 0; i < 8; ++i)
#pragma unroll
                    for (int j = 0; j < 8; ++j)
                        acc[i][j] = fmaf(zf[i], ef[j], acc[i][j]);
            }
        }

        // Chunk epilogue: fold into running argmin (codes ascending -> strict <
        // keeps the lowest index on exact ties, matching jnp.argmin)
#pragma unroll
        for (int j = 0; j < 8; ++j) {
            int code = c0 + tx * 8 + j;
            float eq = g_esq[code];
#pragma unroll
            for (int i = 0; i < 8; ++i) {
                float d = eq - 2.0f * acc[i][j];
                if (d < bestD[i]) { bestD[i] = d; bestI[i] = code; }
            }
        }
    }

    // Cross-lane reduce over the 16 code-groups (width=16 keeps row groups apart)
#pragma unroll
    for (int off = 8; off > 0; off >>= 1) {
#pragma unroll
        for (int i = 0; i < 8; ++i) {
            float od = __shfl_down_sync(0xffffffffu, bestD[i], off, 16);
            int   oi = __shfl_down_sync(0xffffffffu, bestI[i], off, 16);
            if (od < bestD[i] || (od == bestD[i] && oi < bestI[i])) {
                bestD[i] = od; bestI[i] = oi;
            }
        }
    }
    if (tx == 0) {
#pragma unroll
        for (int i = 0; i < 8; ++i)
            g_idx[row0 + ty * 8 + i] = bestI[i];
    }
}

// ---------------------------------------------------------------------------
// Kernel 3: zero accumulators (graph replays must be deterministic)
// ---------------------------------------------------------------------------
__global__ void k_zero() {
    int t = blockIdx.x * blockDim.x + threadIdx.x;
    if (t < KCODES) g_cnt[t] = 0;
    if (t == 0) g_sse = 0.0;
}

// ---------------------------------------------------------------------------
// Kernel 4: gather z_q, write z_q_st = z_e + (z_q - z_e), indices (as float),
// accumulate SSE and histogram counts. One warp per row.
// ---------------------------------------------------------------------------
__global__ void k_gather(const float* __restrict__ z, const float* __restrict__ cb,
                         float* __restrict__ out) {
    int gwarp = (blockIdx.x * blockDim.x + threadIdx.x) >> 5;
    int lane  = threadIdx.x & 31;
    if (gwarp >= N_ROWS) return;
    int row = gwarp;
    int idx = g_idx[row];

    const float4* q  = (const float4*)(cb + (size_t)idx * DIM);
    const float4* ze = (const float4*)(z + (size_t)row * DIM);
    float4*       o  = (float4*)(out + (size_t)row * DIM);

    float s = 0.f;
#pragma unroll
    for (int i = 0; i < 2; ++i) {
        int c = lane + i * 32;
        float4 a = ze[c];
        float4 b = q[c];
        float4 r;
        r.x = a.x + (b.x - a.x);
        r.y = a.y + (b.y - a.y);
        r.z = a.z + (b.z - a.z);
        r.w = a.w + (b.w - a.w);
        float dx = a.x - b.x, dy = a.y - b.y, dz = a.z - b.z, dw = a.w - b.w;
        s += dx * dx + dy * dy + dz * dz + dw * dw;
        o[c] = r;
    }
#pragma unroll
    for (int off = 16; off > 0; off >>= 1)
        s += __shfl_down_sync(0xffffffffu, s, off);

    if (lane == 0) {
        atomicAdd(&g_sse, (double)s);
        atomicAdd(&g_cnt[idx], 1);
        out[NZ + row] = (float)idx;       // indices output (cast to float)
    }
}

// ---------------------------------------------------------------------------
// Kernel 5: loss + perplexity scalars
// ---------------------------------------------------------------------------
__global__ void k_final(float* __restrict__ out) {
    __shared__ float red[256];
    int t = threadIdx.x;
    float h = 0.f;
    for (int c = t; c < KCODES; c += 256) {
        float avg = (float)g_cnt[c] / (float)N_ROWS;
        h += avg * logf(avg + 1e-12f);
    }
    red[t] = h;
    __syncthreads();
    for (int s = 128; s > 0; s >>= 1) {
        if (t < s) red[t] += red[t + s];
        __syncthreads();
    }
    if (t == 0) {
        double mse = g_sse / (double)((size_t)N_ROWS * DIM);
        out[NZ + N_ROWS]     = (float)(1.25 * mse);   // codebook_loss + 0.25*commitment
        out[NZ + N_ROWS + 1] = expf(-red[0]);         // perplexity
    }
}

// ---------------------------------------------------------------------------
extern "C" void kernel_launch(void* const* d_in, const int* in_sizes, int n_in,
                              void* d_out, int out_size) {
    const float* z  = (const float*)d_in[0];   // z_e   [32,32,32,256]
    const float* cb = (const float*)d_in[1];   // codebook [8192,256]
    float* out = (float*)d_out;

    cudaFuncSetAttribute(k_argmin, cudaFuncAttributeMaxDynamicSharedMemorySize,
                         SMEM_BYTES);

    k_esq<<<KCODES / 256, 256>>>(cb);
    k_argmin<<<N_ROWS / BM, 256, SMEM_BYTES>>>(z, cb);
    k_zero<<<KCODES / 256, 256>>>();
    k_gather<<<(N_ROWS * 32) / 256, 256>>>(z, cb, out);
    k_final<<<1, 256>>>(out);
}